// round 6
// baseline (speedup 1.0000x reference)
#include <cuda_runtime.h>
#include <cstdint>

// Problem constants (fixed by the dataset)
#define T_TOK   16384
#define D_DIM   4096
#define E_EXP   64
#define BM      128             // tokens per block
#define BK      32              // fp32 k per chunk (4 k8 steps)
#define NCHUNK  (D_DIM / BK)    // 128
#define NBLK    (T_TOK / BM)    // 128
#define NT      256

// (hi,lo) pair tiles, PS=12 pairs/row, per-ks lut offsets for bank spread
// A: [mt 0..7][ks 0..3][row 0..15][col 0..7]  mt stride 784 pairs
// B: [nt 0..7][ks 0..3][row 0..7 ][col 0..7]  nt stride 400 pairs
#define A_MT_B    6272          // 784 pairs * 8 bytes
#define B_NT_B    3200          // 400 pairs * 8
#define B_OFF     50176         // 8 * A_MT_B
#define STAGE_SZ  75776         // B_OFF + 8 * B_NT_B
#define SMEM_BYTES (2 * STAGE_SZ)   // 151552

static __device__ float g_ssum[NBLK * E_EXP];
static __device__ int   g_cnt [NBLK * E_EXP];
static __device__ int   g_arrived;   // zero-init; reset by last block each launch

// pair-unit ks base offsets (mod-16 pattern {0,2,8,10} -> conflict-free banks)
#define KSA0 0
#define KSA1 194
#define KSA2 392
#define KSA3 586
#define KSB0 0
#define KSB1 98
#define KSB2 200
#define KSB3 298

// ---------- helpers ----------
__device__ __forceinline__ uint32_t smem_u32(const void* p) {
    uint32_t a;
    asm("{ .reg .u64 t; cvta.to.shared.u64 t, %1; cvt.u32.u64 %0, t; }" : "=r"(a) : "l"(p));
    return a;
}
__device__ __forceinline__ uint32_t tf32r(float x) {    // round-to-nearest tf32
    uint32_t r; asm("cvt.rna.tf32.f32 %0, %1;" : "=r"(r) : "f"(x)); return r;
}
__device__ __forceinline__ void ld2(uint32_t a, uint32_t& h, uint32_t& l) {
    asm volatile("ld.shared.v2.u32 {%0,%1}, [%2];" : "=r"(h), "=r"(l) : "r"(a));
}
__device__ __forceinline__ void st4u(uint32_t a, uint32_t x, uint32_t y, uint32_t z, uint32_t w) {
    asm volatile("st.shared.v4.u32 [%0], {%1,%2,%3,%4};" :: "r"(a), "r"(x), "r"(y), "r"(z), "r"(w));
}
__device__ __forceinline__ void mma_tf32(float* d, uint32_t a0, uint32_t a1, uint32_t a2,
                                         uint32_t a3, uint32_t b0, uint32_t b1) {
    asm volatile(
        "mma.sync.aligned.m16n8k8.row.col.f32.tf32.tf32.f32 "
        "{%0,%1,%2,%3}, {%4,%5,%6,%7}, {%8,%9}, {%0,%1,%2,%3};"
        : "+f"(d[0]), "+f"(d[1]), "+f"(d[2]), "+f"(d[3])
        : "r"(a0), "r"(a1), "r"(a2), "r"(a3), "r"(b0), "r"(b1));
}

// ---------- single fused kernel ----------
__global__ void __launch_bounds__(NT, 1)
gate_main(const float* __restrict__ inp, const float* __restrict__ W,
          const float* __restrict__ bias, float* __restrict__ out)
{
    extern __shared__ char dsm[];
    __shared__ float s_inv[BM];
    __shared__ float s_ps[NT];
    __shared__ float s_b[E_EXP];
    __shared__ int   s_cnt[E_EXP];
    __shared__ int   s_last;
    __shared__ float rs2[NT];
    __shared__ int   rc2[NT];

    const uint32_t sb = smem_u32(dsm);
    const int tid = threadIdx.x;
    const int blk = blockIdx.x;
    const int w   = tid >> 5;
    const int l   = tid & 31;
    const int l4  = l >> 2;
    const int lk  = l & 3;
    const int tg  = w >> 1;       // 4 token groups of 32 tokens
    const int eg  = w & 1;        // 2 expert groups of 32 experts

    if (tid < E_EXP) { s_b[tid] = bias[tid]; s_cnt[tid] = 0; }

    const int ksA[4] = {KSA0, KSA1, KSA2, KSA3};
    const int ksB[4] = {KSB0, KSB1, KSB2, KSB3};

    // ---- staging pointers + pair-layout STS bases (chunk-invariant) ----
    // A: 1024 float4/chunk / 256 thr = 4 ; B: 512 / 256 = 2
    const float4* pA[4]; uint32_t stA[4];
#pragma unroll
    for (int p = 0; p < 4; ++p) {
        int idx = p * NT + tid, row = idx >> 3, q = idx & 7;
        pA[p]  = (const float4*)(inp + (size_t)(blk * BM + row) * D_DIM) + q;
        stA[p] = (uint32_t)(((row >> 4) * 784 + ksA[q >> 1] + (row & 15) * 12 + (q & 1) * 4) * 8);
    }
    const float4* pW[2]; uint32_t stW[2];
#pragma unroll
    for (int p = 0; p < 2; ++p) {
        int idx = p * NT + tid, n = idx >> 3, q = idx & 7;
        pW[p]  = (const float4*)(W + (size_t)n * D_DIM) + q;
        stW[p] = (uint32_t)(B_OFF + ((n >> 3) * 400 + ksB[q >> 1] + (n & 7) * 12 + (q & 1) * 4) * 8);
    }

    // compute-side fragment base addresses (per tile; ks offset folds to imm)
    const uint32_t fr = (uint32_t)((l4 * 12 + lk) * 8);
    uint32_t fA[2], fB[4];
#pragma unroll
    for (int i = 0; i < 2; ++i) fA[i] = (uint32_t)((tg * 2 + i) * A_MT_B) + fr;
#pragma unroll
    for (int j = 0; j < 4; ++j) fB[j] = (uint32_t)(B_OFF + (eg * 4 + j) * B_NT_B) + fr;

    float acc[2][4][4];
#pragma unroll
    for (int i = 0; i < 2; ++i)
#pragma unroll
        for (int j = 0; j < 4; ++j)
#pragma unroll
            for (int r = 0; r < 4; ++r) acc[i][j][r] = 0.f;

    float4 ra[4], rw[2];
#pragma unroll
    for (int p = 0; p < 4; ++p) ra[p] = pA[p][0];
#pragma unroll
    for (int p = 0; p < 2; ++p) rw[p] = pW[p][0];

    // fragment double buffers
    uint32_t aH[2][2][4], aL[2][2][4], bH[2][4][2], bL[2][4][2];

    for (int c = 0; c < NCHUNK; ++c) {
        const uint32_t tb = sb + (c & 1) * STAGE_SZ;
        // split fp32 -> (tf32 hi, fp32 lo) pairs, store interleaved (2x st.v4 each)
#pragma unroll
        for (int p = 0; p < 4; ++p) {
            float4 v = ra[p];
            uint32_t hx = tf32r(v.x), hy = tf32r(v.y), hz = tf32r(v.z), hw = tf32r(v.w);
            uint32_t a = tb + stA[p];
            st4u(a,      hx, __float_as_uint(v.x - __uint_as_float(hx)),
                         hy, __float_as_uint(v.y - __uint_as_float(hy)));
            st4u(a + 16, hz, __float_as_uint(v.z - __uint_as_float(hz)),
                         hw, __float_as_uint(v.w - __uint_as_float(hw)));
        }
#pragma unroll
        for (int p = 0; p < 2; ++p) {
            float4 v = rw[p];
            uint32_t hx = tf32r(v.x), hy = tf32r(v.y), hz = tf32r(v.z), hw = tf32r(v.w);
            uint32_t a = tb + stW[p];
            st4u(a,      hx, __float_as_uint(v.x - __uint_as_float(hx)),
                         hy, __float_as_uint(v.y - __uint_as_float(hy)));
            st4u(a + 16, hz, __float_as_uint(v.z - __uint_as_float(hz)),
                         hw, __float_as_uint(v.w - __uint_as_float(hw)));
        }
        __syncthreads();   // dbl-buffer safe: one full sync separates reuse

        if (c + 1 < NCHUNK) {
#pragma unroll
            for (int p = 0; p < 4; ++p) ra[p] = pA[p][(c + 1) * (BK / 4)];
#pragma unroll
            for (int p = 0; p < 2; ++p) rw[p] = pW[p][(c + 1) * (BK / 4)];
        }

        // preload ks=0 fragments
#pragma unroll
        for (int i = 0; i < 2; ++i) {
            uint32_t a = tb + fA[i] + KSA0 * 8;
            ld2(a,       aH[0][i][0], aL[0][i][0]);
            ld2(a + 768, aH[0][i][1], aL[0][i][1]);
            ld2(a + 32,  aH[0][i][2], aL[0][i][2]);
            ld2(a + 800, aH[0][i][3], aL[0][i][3]);
        }
#pragma unroll
        for (int j = 0; j < 4; ++j) {
            uint32_t a = tb + fB[j] + KSB0 * 8;
            ld2(a,      bH[0][j][0], bL[0][j][0]);
            ld2(a + 32, bH[0][j][1], bL[0][j][1]);
        }

#pragma unroll
        for (int ks = 0; ks < 4; ++ks) {
            const int cur = ks & 1, nxt = cur ^ 1;
            if (ks < 3) {
                const uint32_t oA = (uint32_t)(ksA[ks + 1] * 8);
                const uint32_t oB = (uint32_t)(ksB[ks + 1] * 8);
#pragma unroll
                for (int i = 0; i < 2; ++i) {
                    uint32_t a = tb + fA[i] + oA;
                    ld2(a,       aH[nxt][i][0], aL[nxt][i][0]);
                    ld2(a + 768, aH[nxt][i][1], aL[nxt][i][1]);
                    ld2(a + 32,  aH[nxt][i][2], aL[nxt][i][2]);
                    ld2(a + 800, aH[nxt][i][3], aL[nxt][i][3]);
                }
#pragma unroll
                for (int j = 0; j < 4; ++j) {
                    uint32_t a = tb + fB[j] + oB;
                    ld2(a,      bH[nxt][j][0], bL[nxt][j][0]);
                    ld2(a + 32, bH[nxt][j][1], bL[nxt][j][1]);
                }
            }
            // 3 rounds of 8 independent MMAs (RAW distance 8)
#pragma unroll
            for (int i = 0; i < 2; ++i)
#pragma unroll
                for (int j = 0; j < 4; ++j)
                    mma_tf32(acc[i][j], aH[cur][i][0], aH[cur][i][1], aH[cur][i][2],
                             aH[cur][i][3], bH[cur][j][0], bH[cur][j][1]);
#pragma unroll
            for (int i = 0; i < 2; ++i)
#pragma unroll
                for (int j = 0; j < 4; ++j)
                    mma_tf32(acc[i][j], aH[cur][i][0], aH[cur][i][1], aH[cur][i][2],
                             aH[cur][i][3], bL[cur][j][0], bL[cur][j][1]);
#pragma unroll
            for (int i = 0; i < 2; ++i)
#pragma unroll
                for (int j = 0; j < 4; ++j)
                    mma_tf32(acc[i][j], aL[cur][i][0], aL[cur][i][1], aL[cur][i][2],
                             aL[cur][i][3], bH[cur][j][0], bH[cur][j][1]);
        }
    }
    __syncthreads();   // compute done before logits overlay tile buffers

    // ---- epilogue: fragments -> smem logits [128][65] ----
    float* Ls = (float*)dsm;
#pragma unroll
    for (int i = 0; i < 2; ++i) {
        int t0 = tg * 32 + i * 16 + l4;
#pragma unroll
        for (int j = 0; j < 4; ++j) {
            int e0 = eg * 32 + j * 8 + lk * 2;
            Ls[t0 * 65 + e0]           = acc[i][j][0];
            Ls[t0 * 65 + e0 + 1]       = acc[i][j][1];
            Ls[(t0 + 8) * 65 + e0]     = acc[i][j][2];
            Ls[(t0 + 8) * 65 + e0 + 1] = acc[i][j][3];
        }
    }
    __syncthreads();

    // per-token softmax / argmax (threads 0..127); store exp() back
    if (tid < BM) {
        float* lr = &Ls[tid * 65];
        float m = -1e30f; int am = 0;
#pragma unroll
        for (int e = 0; e < E_EXP; ++e) {
            float v = lr[e] + s_b[e];
            lr[e] = v;
            if (v > m) { m = v; am = e; }
        }
        float den = 0.f;
#pragma unroll
        for (int e = 0; e < E_EXP; ++e) {
            float p = expf(lr[e] - m);
            lr[e] = p;
            den += p;
        }
        float inv = 1.f / den;
        s_inv[tid] = inv;
        atomicAdd(&s_cnt[am], 1);          // int atomic: value-deterministic
        int gt = blk * BM + tid;
        out[gt]         = (float)am;       // pruned_idx (capacity 39322 > T: never pruned)
        out[T_TOK + gt] = inv;             // top1 score = exp(0)/den
    }
    __syncthreads();

    // per-expert score partial sums (fixed deterministic order; 4 slices of 32 tokens)
    {
        int e = tid & 63, h = tid >> 6;
        float s = 0.f;
#pragma unroll
        for (int i = 0; i < 32; ++i) {
            int t = h * 32 + i;
            s += Ls[t * 65 + e] * s_inv[t];
        }
        s_ps[tid] = s;
    }
    __syncthreads();
    if (tid < E_EXP) {
        g_ssum[blk * E_EXP + tid] = s_ps[tid] + s_ps[64 + tid] + s_ps[128 + tid] + s_ps[192 + tid];
        g_cnt [blk * E_EXP + tid] = s_cnt[tid];
    }
    __syncthreads();

    // ---- fused loss: last block reduces (deterministic fixed-order) ----
    if (tid == 0) {
        __threadfence();
        int n = atomicAdd(&g_arrived, 1);
        s_last = (n == NBLK - 1) ? 1 : 0;
    }
    __syncthreads();
    if (s_last) {
        __threadfence();
        int e = tid & 63, h = tid >> 6;      // 4 groups of 32 blocks
        float ss = 0.f; int c = 0;
#pragma unroll
        for (int b = h * 32; b < h * 32 + 32; ++b) {
            ss += g_ssum[b * E_EXP + e];
            c  += g_cnt [b * E_EXP + e];
        }
        rs2[tid] = ss; rc2[tid] = c;
        __syncthreads();
        if (tid < E_EXP) {
            float S = rs2[tid] + rs2[64 + tid] + rs2[128 + tid] + rs2[192 + tid];
            int   C = rc2[tid] + rc2[64 + tid] + rc2[128 + tid] + rc2[192 + tid];
            rs2[tid] = S * (float)C;
        }
        __syncthreads();
        if (tid == 0) {
            float tot = 0.f;
#pragma unroll
            for (int e2 = 0; e2 < E_EXP; ++e2) tot += rs2[e2];
            out[2 * T_TOK] = tot * (float)E_EXP / ((float)T_TOK * (float)T_TOK);
            g_arrived = 0;   // reset for next graph replay
        }
    }
}

extern "C" void kernel_launch(void* const* d_in, const int* in_sizes, int n_in,
                              void* d_out, int out_size)
{
    const float* inp  = (const float*)d_in[0];
    const float* W    = (const float*)d_in[1];
    const float* bias = (const float*)d_in[2];
    float* out = (float*)d_out;   // [0,T) idx, [T,2T) top1 score, [2T] loss

    cudaFuncSetAttribute(gate_main, cudaFuncAttributeMaxDynamicSharedMemorySize, SMEM_BYTES);
    gate_main<<<NBLK, NT, SMEM_BYTES>>>(inp, W, bias, out);
}

// round 8
// speedup vs baseline: 1.5630x; 1.5630x over previous
#include <cuda_runtime.h>
#include <cuda_fp16.h>
#include <cstdint>

// Problem constants (fixed by the dataset)
#define T_TOK   16384
#define D_DIM   4096
#define E_EXP   64
#define BM      128             // tokens per block
#define BK      32              // fp32 k per chunk (2 k16 MMA steps)
#define NCHUNK  (D_DIM / BK)    // 128
#define NBLK    (T_TOK / BM)    // 128
#define NT      256

// fp16 plane tiles, row stride 80 bytes (64B data + 16B pad -> LDSM conflict-free)
#define AH_O      0
#define AL_O      10240          // 128 rows * 80
#define BH_O      20480
#define BL_O      25600          // + 64 * 80
#define STAGE_SZ  30720
#define SMEM_BYTES (2 * STAGE_SZ)   // 61440; epilogue Ls[128][65] = 33280 fits

static __device__ float g_ssum[NBLK * E_EXP];
static __device__ int   g_cnt [NBLK * E_EXP];
static __device__ int   g_arrived;   // zero-init; reset by last block each launch

// ---------- helpers ----------
__device__ __forceinline__ uint32_t smem_u32(const void* p) {
    uint32_t a;
    asm("{ .reg .u64 t; cvta.to.shared.u64 t, %1; cvt.u32.u64 %0, t; }" : "=r"(a) : "l"(p));
    return a;
}
__device__ __forceinline__ void cvt_split2(float x0, float x1, uint32_t& h, uint32_t& lo) {
    __half2 hh = __floats2half2_rn(x0, x1);          // low = x0, high = x1
    h = *reinterpret_cast<uint32_t*>(&hh);
    float2 hf = __half22float2(hh);
    __half2 ll = __floats2half2_rn(x0 - hf.x, x1 - hf.y);
    lo = *reinterpret_cast<uint32_t*>(&ll);
}
__device__ __forceinline__ void st2u(uint32_t a, uint32_t x, uint32_t y) {
    asm volatile("st.shared.v2.u32 [%0], {%1,%2};" :: "r"(a), "r"(x), "r"(y));
}
__device__ __forceinline__ void ldsm4(uint32_t a, uint32_t* r) {
    asm volatile("ldmatrix.sync.aligned.m8n8.x4.shared.b16 {%0,%1,%2,%3}, [%4];"
                 : "=r"(r[0]), "=r"(r[1]), "=r"(r[2]), "=r"(r[3]) : "r"(a));
}
__device__ __forceinline__ void mma_f16(float* d, const uint32_t* a, const uint32_t* b) {
    asm volatile(
        "mma.sync.aligned.m16n8k16.row.col.f32.f16.f16.f32 "
        "{%0,%1,%2,%3}, {%4,%5,%6,%7}, {%8,%9}, {%0,%1,%2,%3};"
        : "+f"(d[0]), "+f"(d[1]), "+f"(d[2]), "+f"(d[3])
        : "r"(a[0]), "r"(a[1]), "r"(a[2]), "r"(a[3]), "r"(b[0]), "r"(b[1]));
}

// ---------- single fused kernel ----------
__global__ void __launch_bounds__(NT, 1)
gate_main(const float* __restrict__ inp, const float* __restrict__ W,
          const float* __restrict__ bias, float* __restrict__ out)
{
    extern __shared__ char dsm[];
    __shared__ float s_inv[BM];
    __shared__ float s_ps[NT];
    __shared__ float s_b[E_EXP];
    __shared__ int   s_cnt[E_EXP];
    __shared__ int   s_last;
    __shared__ float rs2[NT];
    __shared__ int   rc2[NT];

    const uint32_t sb = smem_u32(dsm);
    const int tid = threadIdx.x;
    const int blk = blockIdx.x;
    const int w   = tid >> 5;
    const int l   = tid & 31;
    const int l4  = l >> 2;
    const int lk  = l & 3;
    const int tg  = w >> 1;       // 4 token groups of 32 tokens
    const int eg  = w & 1;        // 2 expert groups of 32 experts

    if (tid < E_EXP) { s_b[tid] = bias[tid]; s_cnt[tid] = 0; }

    // ---- staging pointers + STS bases (chunk-invariant) ----
    // A: 1024 float4/chunk / 256 thr = 4 ; B: 512 / 256 = 2
    const float4* pA[4]; uint32_t stA[4];
#pragma unroll
    for (int p = 0; p < 4; ++p) {
        int idx = p * NT + tid, row = idx >> 3, q = idx & 7;
        pA[p]  = (const float4*)(inp + (size_t)(blk * BM + row) * D_DIM) + q;
        stA[p] = (uint32_t)(row * 80 + q * 8);
    }
    const float4* pW[2]; uint32_t stW[2];
#pragma unroll
    for (int p = 0; p < 2; ++p) {
        int idx = p * NT + tid, n = idx >> 3, q = idx & 7;
        pW[p]  = (const float4*)(W + (size_t)n * D_DIM) + q;
        stW[p] = (uint32_t)(BH_O + n * 80 + q * 8);
    }

    // ---- ldmatrix per-lane addresses (chunk-invariant bases) ----
    // A x4: g0 rows m..m+7 klo | g1 m+8..m+15 klo | g2 m..m+7 khi | g3 m+8.. khi
    uint32_t aLd[2];
#pragma unroll
    for (int i = 0; i < 2; ++i)
        aLd[i] = (uint32_t)(AH_O + ((tg * 2 + i) * 16 + ((l >> 3) & 1) * 8 + (l & 7)) * 80
                            + (l >> 4) * 16);
    // B x4 (NON-trans: W[n][k] row-major == col-major KxN, same pattern as A):
    // g0 rows n..n+7 klo | g1 same rows khi | g2 n+8..n+15 klo | g3 n+8.. khi
    // -> r[0],r[1] = b{0,1} of n-tile jp*2 ; r[2],r[3] = b{0,1} of n-tile jp*2+1
    uint32_t bLd[2];
#pragma unroll
    for (int jp = 0; jp < 2; ++jp)
        bLd[jp] = (uint32_t)(BH_O + (eg * 32 + jp * 16 + (l >> 4) * 8 + (l & 7)) * 80
                             + ((l >> 3) & 1) * 16);

    float acc[2][4][4];
#pragma unroll
    for (int i = 0; i < 2; ++i)
#pragma unroll
        for (int j = 0; j < 4; ++j)
#pragma unroll
            for (int r = 0; r < 4; ++r) acc[i][j][r] = 0.f;

    float4 ra[4], rw[2];
#pragma unroll
    for (int p = 0; p < 4; ++p) ra[p] = pA[p][0];
#pragma unroll
    for (int p = 0; p < 2; ++p) rw[p] = pW[p][0];

    // fragment double buffers over ks
    uint32_t aH[2][2][4], aL[2][2][4], bH[2][4][2], bL[2][4][2];

    for (int c = 0; c < NCHUNK; ++c) {
        const uint32_t tb = sb + (c & 1) * STAGE_SZ;
        // split fp32 -> fp16 hi/lo planes, vectorized 8B stores
#pragma unroll
        for (int p = 0; p < 4; ++p) {
            uint32_t h01, l01, h23, l23;
            cvt_split2(ra[p].x, ra[p].y, h01, l01);
            cvt_split2(ra[p].z, ra[p].w, h23, l23);
            st2u(tb + stA[p],          h01, h23);
            st2u(tb + stA[p] + AL_O,   l01, l23);
        }
#pragma unroll
        for (int p = 0; p < 2; ++p) {
            uint32_t h01, l01, h23, l23;
            cvt_split2(rw[p].x, rw[p].y, h01, l01);
            cvt_split2(rw[p].z, rw[p].w, h23, l23);
            st2u(tb + stW[p],                    h01, h23);
            st2u(tb + stW[p] + (BL_O - BH_O),    l01, l23);
        }
        __syncthreads();   // dbl-buffer safe: one full sync separates buffer reuse

        if (c + 1 < NCHUNK) {
#pragma unroll
            for (int p = 0; p < 4; ++p) ra[p] = pA[p][(c + 1) * (BK / 4)];
#pragma unroll
            for (int p = 0; p < 2; ++p) rw[p] = pW[p][(c + 1) * (BK / 4)];
        }

        // preload ks=0 fragments
#pragma unroll
        for (int i = 0; i < 2; ++i) {
            ldsm4(tb + aLd[i],            aH[0][i]);
            ldsm4(tb + aLd[i] + AL_O,     aL[0][i]);
        }
#pragma unroll
        for (int jp = 0; jp < 2; ++jp) {
            uint32_t r[4];
            ldsm4(tb + bLd[jp], r);
            bH[0][jp * 2][0] = r[0]; bH[0][jp * 2][1] = r[1];
            bH[0][jp * 2 + 1][0] = r[2]; bH[0][jp * 2 + 1][1] = r[3];
            ldsm4(tb + bLd[jp] + (BL_O - BH_O), r);
            bL[0][jp * 2][0] = r[0]; bL[0][jp * 2][1] = r[1];
            bL[0][jp * 2 + 1][0] = r[2]; bL[0][jp * 2 + 1][1] = r[3];
        }

#pragma unroll
        for (int ks = 0; ks < 2; ++ks) {
            if (ks == 0) {   // prefetch ks=1 fragments (+32B = 16 fp16)
#pragma unroll
                for (int i = 0; i < 2; ++i) {
                    ldsm4(tb + aLd[i] + 32,        aH[1][i]);
                    ldsm4(tb + aLd[i] + AL_O + 32, aL[1][i]);
                }
#pragma unroll
                for (int jp = 0; jp < 2; ++jp) {
                    uint32_t r[4];
                    ldsm4(tb + bLd[jp] + 32, r);
                    bH[1][jp * 2][0] = r[0]; bH[1][jp * 2][1] = r[1];
                    bH[1][jp * 2 + 1][0] = r[2]; bH[1][jp * 2 + 1][1] = r[3];
                    ldsm4(tb + bLd[jp] + (BL_O - BH_O) + 32, r);
                    bL[1][jp * 2][0] = r[0]; bL[1][jp * 2][1] = r[1];
                    bL[1][jp * 2 + 1][0] = r[2]; bL[1][jp * 2 + 1][1] = r[3];
                }
            }
            // 3 term-rounds of 8 independent MMAs (RAW distance 8)
#pragma unroll
            for (int i = 0; i < 2; ++i)
#pragma unroll
                for (int j = 0; j < 4; ++j)
                    mma_f16(acc[i][j], aH[ks][i], bH[ks][j]);
#pragma unroll
            for (int i = 0; i < 2; ++i)
#pragma unroll
                for (int j = 0; j < 4; ++j)
                    mma_f16(acc[i][j], aH[ks][i], bL[ks][j]);
#pragma unroll
            for (int i = 0; i < 2; ++i)
#pragma unroll
                for (int j = 0; j < 4; ++j)
                    mma_f16(acc[i][j], aL[ks][i], bH[ks][j]);
        }
    }
    __syncthreads();   // compute done before logits overlay tile buffers

    // ---- epilogue: fragments -> smem logits [128][65] ----
    float* Ls = (float*)dsm;
#pragma unroll
    for (int i = 0; i < 2; ++i) {
        int t0 = tg * 32 + i * 16 + l4;
#pragma unroll
        for (int j = 0; j < 4; ++j) {
            int e0 = eg * 32 + j * 8 + lk * 2;
            Ls[t0 * 65 + e0]           = acc[i][j][0];
            Ls[t0 * 65 + e0 + 1]       = acc[i][j][1];
            Ls[(t0 + 8) * 65 + e0]     = acc[i][j][2];
            Ls[(t0 + 8) * 65 + e0 + 1] = acc[i][j][3];
        }
    }
    __syncthreads();

    // per-token softmax / argmax (threads 0..127); store exp() back
    if (tid < BM) {
        float* lr = &Ls[tid * 65];
        float m = -1e30f; int am = 0;
#pragma unroll
        for (int e = 0; e < E_EXP; ++e) {
            float v = lr[e] + s_b[e];
            lr[e] = v;
            if (v > m) { m = v; am = e; }
        }
        float den = 0.f;
#pragma unroll
        for (int e = 0; e < E_EXP; ++e) {
            float p = expf(lr[e] - m);
            lr[e] = p;
            den += p;
        }
        float inv = 1.f / den;
        s_inv[tid] = inv;
        atomicAdd(&s_cnt[am], 1);          // int atomic: value-deterministic
        int gt = blk * BM + tid;
        out[gt]         = (float)am;       // pruned_idx (capacity 39322 > T: never pruned)
        out[T_TOK + gt] = inv;             // top1 score = exp(0)/den
    }
    __syncthreads();

    // per-expert score partial sums (fixed deterministic order; 4 slices of 32 tokens)
    {
        int e = tid & 63, h = tid >> 6;
        float s = 0.f;
#pragma unroll
        for (int i = 0; i < 32; ++i) {
            int t = h * 32 + i;
            s += Ls[t * 65 + e] * s_inv[t];
        }
        s_ps[tid] = s;
    }
    __syncthreads();
    if (tid < E_EXP) {
        g_ssum[blk * E_EXP + tid] = s_ps[tid] + s_ps[64 + tid] + s_ps[128 + tid] + s_ps[192 + tid];
        g_cnt [blk * E_EXP + tid] = s_cnt[tid];
    }
    __syncthreads();

    // ---- fused loss: last block reduces (deterministic fixed-order) ----
    if (tid == 0) {
        __threadfence();
        int n = atomicAdd(&g_arrived, 1);
        s_last = (n == NBLK - 1) ? 1 : 0;
    }
    __syncthreads();
    if (s_last) {
        __threadfence();
        int e = tid & 63, h = tid >> 6;      // 4 groups of 32 blocks
        float ss = 0.f; int c = 0;
#pragma unroll
        for (int b = h * 32; b < h * 32 + 32; ++b) {
            ss += g_ssum[b * E_EXP + e];
            c  += g_cnt [b * E_EXP + e];
        }
        rs2[tid] = ss; rc2[tid] = c;
        __syncthreads();
        if (tid < E_EXP) {
            float S = rs2[tid] + rs2[64 + tid] + rs2[128 + tid] + rs2[192 + tid];
            int   C = rc2[tid] + rc2[64 + tid] + rc2[128 + tid] + rc2[192 + tid];
            rs2[tid] = S * (float)C;
        }
        __syncthreads();
        if (tid == 0) {
            float tot = 0.f;
#pragma unroll
            for (int e2 = 0; e2 < E_EXP; ++e2) tot += rs2[e2];
            out[2 * T_TOK] = tot * (float)E_EXP / ((float)T_TOK * (float)T_TOK);
            g_arrived = 0;   // reset for next graph replay
        }
    }
}

extern "C" void kernel_launch(void* const* d_in, const int* in_sizes, int n_in,
                              void* d_out, int out_size)
{
    const float* inp  = (const float*)d_in[0];
    const float* W    = (const float*)d_in[1];
    const float* bias = (const float*)d_in[2];
    float* out = (float*)d_out;   // [0,T) idx, [T,2T) top1 score, [2T] loss

    cudaFuncSetAttribute(gate_main, cudaFuncAttributeMaxDynamicSharedMemorySize, SMEM_BYTES);
    gate_main<<<NBLK, NT, SMEM_BYTES>>>(inp, W, bias, out);
}

// round 9
// speedup vs baseline: 2.0733x; 1.3265x over previous
#include <cuda_runtime.h>
#include <cuda_fp16.h>
#include <cstdint>

// Problem constants (fixed by the dataset)
#define T_TOK   16384
#define D_DIM   4096
#define E_EXP   64
#define BM      128             // tokens per block
#define BK      64              // fp32 k per chunk (4 k16 steps, split 2+2 across kh pairs)
#define NCHUNK  (D_DIM / BK)    // 64
#define NBLK    (T_TOK / BM)    // 128
#define NT      256

// fp16 plane tiles, row stride 144 B (128B data + 16B pad -> LDSM conflict-free)
#define RSB       144
#define AH_O      0
#define AL_O      18432          // 128 rows * 144
#define BH_O      36864
#define BL_O      46080          // + 64 * 144
#define STAGE_SZ  55296
#define SMEM_BYTES (2 * STAGE_SZ)   // 110592; epilogue Ls[128][65]=33280 overlays stage0

static __device__ float g_ssum[NBLK * E_EXP];
static __device__ int   g_cnt [NBLK * E_EXP];
static __device__ int   g_arrived;   // zero-init; reset by last block each launch

// ---------- helpers ----------
__device__ __forceinline__ uint32_t smem_u32(const void* p) {
    uint32_t a;
    asm("{ .reg .u64 t; cvta.to.shared.u64 t, %1; cvt.u32.u64 %0, t; }" : "=r"(a) : "l"(p));
    return a;
}
__device__ __forceinline__ void cvt_split2(float x0, float x1, uint32_t& h, uint32_t& lo) {
    __half2 hh = __floats2half2_rn(x0, x1);          // low = x0, high = x1
    h = *reinterpret_cast<uint32_t*>(&hh);
    float2 hf = __half22float2(hh);
    __half2 ll = __floats2half2_rn(x0 - hf.x, x1 - hf.y);
    lo = *reinterpret_cast<uint32_t*>(&ll);
}
__device__ __forceinline__ void st2u(uint32_t a, uint32_t x, uint32_t y) {
    asm volatile("st.shared.v2.u32 [%0], {%1,%2};" :: "r"(a), "r"(x), "r"(y));
}
__device__ __forceinline__ void ldsm4(uint32_t a, uint32_t* r) {
    asm volatile("ldmatrix.sync.aligned.m8n8.x4.shared.b16 {%0,%1,%2,%3}, [%4];"
                 : "=r"(r[0]), "=r"(r[1]), "=r"(r[2]), "=r"(r[3]) : "r"(a));
}
__device__ __forceinline__ void mma_f16(float* d, const uint32_t* a, const uint32_t* b) {
    asm volatile(
        "mma.sync.aligned.m16n8k16.row.col.f32.f16.f16.f32 "
        "{%0,%1,%2,%3}, {%4,%5,%6,%7}, {%8,%9}, {%0,%1,%2,%3};"
        : "+f"(d[0]), "+f"(d[1]), "+f"(d[2]), "+f"(d[3])
        : "r"(a[0]), "r"(a[1]), "r"(a[2]), "r"(a[3]), "r"(b[0]), "r"(b[1]));
}

// ---------- single fused kernel ----------
__global__ void __launch_bounds__(NT, 1)
gate_main(const float* __restrict__ inp, const float* __restrict__ W,
          const float* __restrict__ bias, float* __restrict__ out)
{
    extern __shared__ char dsm[];
    __shared__ float s_inv[BM];
    __shared__ float s_ps[NT];
    __shared__ float s_b[E_EXP];
    __shared__ int   s_cnt[E_EXP];
    __shared__ int   s_last;
    __shared__ float rs2[NT];
    __shared__ int   rc2[NT];

    const uint32_t sb = smem_u32(dsm);
    const int tid = threadIdx.x;
    const int blk = blockIdx.x;
    const int w   = tid >> 5;
    const int l   = tid & 31;
    const int l4  = l >> 2;
    const int lk  = l & 3;
    const int tg  = (w >> 2) & 1;   // 2 token groups of 64 tokens
    const int eg  = (w >> 1) & 1;   // 2 expert groups of 32 experts
    const int kh  = w & 1;          // k-half split within each chunk

    if (tid < E_EXP) { s_b[tid] = bias[tid]; s_cnt[tid] = 0; }

    // ---- staging assignments: fid -> (row, q4); LDG.128 16-lane contiguous ----
    // A: 2048 float4/chunk / 256 thr = 8 ; W: 1024 / 256 = 4
    const float4* baseA = (const float4*)(inp + (size_t)blk * BM * D_DIM);
    const float4* baseW = (const float4*)W;
    int offA[8]; uint32_t stA[8];
#pragma unroll
    for (int p = 0; p < 8; ++p) {
        int fid = p * NT + tid, row = fid >> 4, q4 = fid & 15;
        offA[p] = row * (D_DIM / 4) + q4;
        stA[p]  = (uint32_t)(row * RSB + q4 * 8);
    }
    int offW[4]; uint32_t stW[4];
#pragma unroll
    for (int p = 0; p < 4; ++p) {
        int fid = p * NT + tid, row = fid >> 4, q4 = fid & 15;
        offW[p] = row * (D_DIM / 4) + q4;
        stW[p]  = (uint32_t)(BH_O + row * RSB + q4 * 8);
    }

    // ---- ldmatrix per-lane base addresses ----
    // A x4: g0 rows m..m+7 klo | g1 m+8..m+15 klo | g2 m..m+7 khi | g3 m+8.. khi
    uint32_t aLd[4];
#pragma unroll
    for (int i = 0; i < 4; ++i)
        aLd[i] = (uint32_t)((tg * 64 + i * 16 + ((l >> 3) & 1) * 8 + (l & 7)) * RSB
                            + (l >> 4) * 16);
    // B x4 (non-trans; W[n][k] row-major == KxN col-major):
    // g0 n..n+7 klo | g1 same khi | g2 n+8..n+15 klo | g3 khi
    uint32_t bLd[2];
#pragma unroll
    for (int jp = 0; jp < 2; ++jp)
        bLd[jp] = (uint32_t)(BH_O + (eg * 32 + jp * 16 + (l >> 4) * 8 + (l & 7)) * RSB
                             + ((l >> 3) & 1) * 16);

    float acc[4][4][4];
#pragma unroll
    for (int i = 0; i < 4; ++i)
#pragma unroll
        for (int j = 0; j < 4; ++j)
#pragma unroll
            for (int r = 0; r < 4; ++r) acc[i][j][r] = 0.f;

    float4 ra[8], rw[4];
#pragma unroll
    for (int p = 0; p < 8; ++p) ra[p] = baseA[offA[p]];
#pragma unroll
    for (int p = 0; p < 4; ++p) rw[p] = baseW[offW[p]];

    for (int c = 0; c < NCHUNK; ++c) {
        const uint32_t tb = sb + (c & 1) * STAGE_SZ;
        // split fp32 -> fp16 hi/lo planes (8B stores, phase-conflict-free)
#pragma unroll
        for (int p = 0; p < 8; ++p) {
            uint32_t h01, l01, h23, l23;
            cvt_split2(ra[p].x, ra[p].y, h01, l01);
            cvt_split2(ra[p].z, ra[p].w, h23, l23);
            st2u(tb + stA[p],        h01, h23);
            st2u(tb + stA[p] + AL_O, l01, l23);
        }
#pragma unroll
        for (int p = 0; p < 4; ++p) {
            uint32_t h01, l01, h23, l23;
            cvt_split2(rw[p].x, rw[p].y, h01, l01);
            cvt_split2(rw[p].z, rw[p].w, h23, l23);
            st2u(tb + stW[p],                  h01, h23);
            st2u(tb + stW[p] + (BL_O - BH_O),  l01, l23);
        }
        __syncthreads();   // dbl-buffer: one full sync separates buffer reuse

        if (c + 1 < NCHUNK) {
#pragma unroll
            for (int p = 0; p < 8; ++p) ra[p] = baseA[offA[p] + (c + 1) * (BK / 4)];
#pragma unroll
            for (int p = 0; p < 4; ++p) rw[p] = baseW[offW[p] + (c + 1) * (BK / 4)];
        }

        // this warp's two k16 steps (kh-split: pair warp covers the other two)
#pragma unroll
        for (int ks2 = 0; ks2 < 2; ++ks2) {
            const uint32_t ko = (uint32_t)((kh * 2 + ks2) * 32);
            uint32_t aH[4][4], aL[4][4], bHf[4][2], bLf[4][2];
#pragma unroll
            for (int i = 0; i < 4; ++i) {
                ldsm4(tb + aLd[i] + ko,        aH[i]);
                ldsm4(tb + aLd[i] + ko + AL_O, aL[i]);
            }
#pragma unroll
            for (int jp = 0; jp < 2; ++jp) {
                uint32_t r[4];
                ldsm4(tb + bLd[jp] + ko, r);
                bHf[jp * 2][0] = r[0]; bHf[jp * 2][1] = r[1];
                bHf[jp * 2 + 1][0] = r[2]; bHf[jp * 2 + 1][1] = r[3];
                ldsm4(tb + bLd[jp] + ko + (BL_O - BH_O), r);
                bLf[jp * 2][0] = r[0]; bLf[jp * 2][1] = r[1];
                bLf[jp * 2 + 1][0] = r[2]; bLf[jp * 2 + 1][1] = r[3];
            }
            // 3 term-rounds of 16 independent MMAs (RAW distance 16)
#pragma unroll
            for (int i = 0; i < 4; ++i)
#pragma unroll
                for (int j = 0; j < 4; ++j)
                    mma_f16(acc[i][j], aH[i], bHf[j]);
#pragma unroll
            for (int i = 0; i < 4; ++i)
#pragma unroll
                for (int j = 0; j < 4; ++j)
                    mma_f16(acc[i][j], aH[i], bLf[j]);
#pragma unroll
            for (int i = 0; i < 4; ++i)
#pragma unroll
                for (int j = 0; j < 4; ++j)
                    mma_f16(acc[i][j], aL[i], bHf[j]);
        }
    }
    __syncthreads();   // compute done before logits overlay tile buffers

    // ---- epilogue: zero Ls, merge kh-pairs via 2-operand atomicAdd (deterministic) ----
    float* Ls = (float*)dsm;   // [128][65]
    for (int idx = tid; idx < BM * 65; idx += NT) Ls[idx] = 0.f;
    __syncthreads();
#pragma unroll
    for (int i = 0; i < 4; ++i) {
        int t0 = tg * 64 + i * 16 + l4;
#pragma unroll
        for (int j = 0; j < 4; ++j) {
            int e0 = eg * 32 + j * 8 + lk * 2;
            atomicAdd(&Ls[t0 * 65 + e0],           acc[i][j][0]);
            atomicAdd(&Ls[t0 * 65 + e0 + 1],       acc[i][j][1]);
            atomicAdd(&Ls[(t0 + 8) * 65 + e0],     acc[i][j][2]);
            atomicAdd(&Ls[(t0 + 8) * 65 + e0 + 1], acc[i][j][3]);
        }
    }
    __syncthreads();

    // per-token softmax / argmax (threads 0..127); store exp() back
    if (tid < BM) {
        float* lr = &Ls[tid * 65];
        float m = -1e30f; int am = 0;
#pragma unroll
        for (int e = 0; e < E_EXP; ++e) {
            float v = lr[e] + s_b[e];
            lr[e] = v;
            if (v > m) { m = v; am = e; }
        }
        float den = 0.f;
#pragma unroll
        for (int e = 0; e < E_EXP; ++e) {
            float p = expf(lr[e] - m);
            lr[e] = p;
            den += p;
        }
        float inv = 1.f / den;
        s_inv[tid] = inv;
        atomicAdd(&s_cnt[am], 1);          // int atomic: value-deterministic
        int gt = blk * BM + tid;
        out[gt]         = (float)am;       // pruned_idx (capacity 39322 > T: never pruned)
        out[T_TOK + gt] = inv;             // top1 score = exp(0)/den
    }
    __syncthreads();

    // per-expert score partial sums (fixed deterministic order; 4 slices of 32 tokens)
    {
        int e = tid & 63, h = tid >> 6;
        float s = 0.f;
#pragma unroll
        for (int i = 0; i < 32; ++i) {
            int t = h * 32 + i;
            s += Ls[t * 65 + e] * s_inv[t];
        }
        s_ps[tid] = s;
    }
    __syncthreads();
    if (tid < E_EXP) {
        g_ssum[blk * E_EXP + tid] = s_ps[tid] + s_ps[64 + tid] + s_ps[128 + tid] + s_ps[192 + tid];
        g_cnt [blk * E_EXP + tid] = s_cnt[tid];
    }
    __syncthreads();

    // ---- fused loss: last block reduces (deterministic fixed-order) ----
    if (tid == 0) {
        __threadfence();
        int n = atomicAdd(&g_arrived, 1);
        s_last = (n == NBLK - 1) ? 1 : 0;
    }
    __syncthreads();
    if (s_last) {
        __threadfence();
        int e = tid & 63, h = tid >> 6;      // 4 groups of 32 blocks
        float ss = 0.f; int c = 0;
#pragma unroll
        for (int b = h * 32; b < h * 32 + 32; ++b) {
            ss += g_ssum[b * E_EXP + e];
            c  += g_cnt [b * E_EXP + e];
        }
        rs2[tid] = ss; rc2[tid] = c;
        __syncthreads();
        if (tid < E_EXP) {
            float S = rs2[tid] + rs2[64 + tid] + rs2[128 + tid] + rs2[192 + tid];
            int   C = rc2[tid] + rc2[64 + tid] + rc2[128 + tid] + rc2[192 + tid];
            rs2[tid] = S * (float)C;
        }
        __syncthreads();
        if (tid == 0) {
            float tot = 0.f;
#pragma unroll
            for (int e2 = 0; e2 < E_EXP; ++e2) tot += rs2[e2];
            out[2 * T_TOK] = tot * (float)E_EXP / ((float)T_TOK * (float)T_TOK);
            g_arrived = 0;   // reset for next graph replay
        }
    }
}

extern "C" void kernel_launch(void* const* d_in, const int* in_sizes, int n_in,
                              void* d_out, int out_size)
{
    const float* inp  = (const float*)d_in[0];
    const float* W    = (const float*)d_in[1];
    const float* bias = (const float*)d_in[2];
    float* out = (float*)d_out;   // [0,T) idx, [T,2T) top1 score, [2T] loss

    cudaFuncSetAttribute(gate_main, cudaFuncAttributeMaxDynamicSharedMemorySize, SMEM_BYTES);
    gate_main<<<NBLK, NT, SMEM_BYTES>>>(inp, W, bias, out);
}